// round 14
// baseline (speedup 1.0000x reference)
#include <cuda_runtime.h>
#include <cstdint>

#define NPTS 262144
#define DIMS 128
#define KCL  1024
#define TM   128
#define TN   128
#define NTILES (KCL / TN)   // 8
#define NTHR 256

// ---- smem map (dynamic, from 1KB-aligned base) ----
#define SM_XI8 0                     // 16KB X int8 tile (swizzled 128B rows)
#define SM_C   16384                 // 2 buffers x 16KB (C int8)
#define SM_CC  49152                 // 8KB: float2[1024] {csq+64, -2*sc}
#define SM_SX  57344                 // 512B: per-point scale
#define SM_BYTES (SM_SX + 512 + 1024)

__device__ __align__(16) unsigned char g_ci8[KCL * DIMS];   // int8 C, row-major
__device__ __align__(16) float2 g_cc[KCL];                  // {csq+64, -2*sc}

// ---------------- PTX helpers (sm_80+ baseline ISA only) ----------------
__device__ __forceinline__ uint32_t smem_u32(const void* p) {
    uint32_t a;
    asm("{ .reg .u64 t; cvta.to.shared.u64 t, %1; cvt.u32.u64 %0, t; }" : "=r"(a) : "l"(p));
    return a;
}
#define LDSM_X4(r0, r1, r2, r3, addr) \
    asm volatile("ldmatrix.sync.aligned.m8n8.x4.shared.b16 {%0,%1,%2,%3}, [%4];" \
                 : "=r"(r0), "=r"(r1), "=r"(r2), "=r"(r3) : "r"(addr))
#define MMA_S8(d, a, b) \
    asm volatile("mma.sync.aligned.m16n8k32.row.col.s32.s8.s8.s32 " \
                 "{%0,%1,%2,%3}, {%4,%5,%6,%7}, {%8,%9}, {%0,%1,%2,%3};" \
                 : "+r"((d)[0]), "+r"((d)[1]), "+r"((d)[2]), "+r"((d)[3]) \
                 : "r"((a)[0]), "r"((a)[1]), "r"((a)[2]), "r"((a)[3]), \
                   "r"((b)[0]), "r"((b)[1]))
#define CP_ASYNC16(dst, src) \
    asm volatile("cp.async.cg.shared.global [%0], [%1], 16;" :: "r"(dst), "l"(src))
#define CP_COMMIT() asm volatile("cp.async.commit_group;" ::: "memory")
#define CP_WAIT(n)  asm volatile("cp.async.wait_group %0;" :: "n"(n) : "memory")

__device__ __forceinline__ uint32_t pack4(int q0, int q1, int q2, int q3) {
    return (uint32_t)(q0 & 255) | ((uint32_t)(q1 & 255) << 8) |
           ((uint32_t)(q2 & 255) << 16) | ((uint32_t)(q3 & 255) << 24);
}

// ---------------- prep: quantize C rows (int8) + csq/scale table ----------------
__global__ void prep_kernel(const float* __restrict__ C) {
    int c = blockIdx.x * blockDim.x + threadIdx.x;
    if (c >= KCL) return;
    const float4* row = (const float4*)(C + (size_t)c * DIMS);
    float f[DIMS];
    float amax = 0.f, sq = 0.f;
#pragma unroll
    for (int i = 0; i < DIMS / 4; i++) {
        float4 v = row[i];
        f[4 * i] = v.x; f[4 * i + 1] = v.y; f[4 * i + 2] = v.z; f[4 * i + 3] = v.w;
        sq += v.x * v.x + v.y * v.y + v.z * v.z + v.w * v.w;
        amax = fmaxf(amax, fmaxf(fmaxf(fabsf(v.x), fabsf(v.y)),
                                 fmaxf(fabsf(v.z), fabsf(v.w))));
    }
    float sc  = amax * (1.f / 127.f);
    float inv = amax > 0.f ? 127.f / amax : 0.f;
    uint4* dst = (uint4*)(g_ci8 + (size_t)c * DIMS);
#pragma unroll
    for (int i = 0; i < 8; i++) {
        uint4 u;
        u.x = pack4(__float2int_rn(f[16*i+ 0]*inv), __float2int_rn(f[16*i+ 1]*inv),
                    __float2int_rn(f[16*i+ 2]*inv), __float2int_rn(f[16*i+ 3]*inv));
        u.y = pack4(__float2int_rn(f[16*i+ 4]*inv), __float2int_rn(f[16*i+ 5]*inv),
                    __float2int_rn(f[16*i+ 6]*inv), __float2int_rn(f[16*i+ 7]*inv));
        u.z = pack4(__float2int_rn(f[16*i+ 8]*inv), __float2int_rn(f[16*i+ 9]*inv),
                    __float2int_rn(f[16*i+10]*inv), __float2int_rn(f[16*i+11]*inv));
        u.w = pack4(__float2int_rn(f[16*i+12]*inv), __float2int_rn(f[16*i+13]*inv),
                    __float2int_rn(f[16*i+14]*inv), __float2int_rn(f[16*i+15]*inv));
        dst[i] = u;
    }
    g_cc[c] = make_float2(sq + 64.f, -2.f * sc);   // bias keeps rank keys > 0
}

// ---------------- main fused kernel ----------------
__global__ void __launch_bounds__(NTHR, 2)
kmeans_mma_kernel(const float* __restrict__ X, const float* __restrict__ Cf,
                  float* __restrict__ out)
{
    extern __shared__ unsigned char smraw[];
    uint32_t base = (smem_u32(smraw) + 1023u) & ~1023u;
    unsigned char* sm = smraw + (base - smem_u32(smraw));

    const int t    = threadIdx.x;
    const int lane = t & 31;
    const int wid  = t >> 5;
    const int wm   = wid & 1;    // warp row  (64 pts)
    const int wn   = wid >> 1;   // warp col  (32 clusters)
    const int pbase = blockIdx.x * TM;

    auto cp_tile = [&](int ct, int buf) {
        uint32_t dbase = base + SM_C + buf * 16384;
#pragma unroll
        for (int i = 0; i < 4; i++) {
            int idx = t + NTHR * i;          // 1024 chunks of 16B
            int row = idx >> 3;
            int ch  = idx & 7;
            uint32_t doff = (uint32_t)row * 128 + (uint32_t)((ch ^ (row & 7)) << 4);
            size_t   soff = (size_t)ct * 16384 + (size_t)row * 128 + (size_t)ch * 16;
            CP_ASYNC16(dbase + doff, g_ci8 + soff);
        }
        CP_COMMIT();
    };
    cp_tile(0, 0);
    cp_tile(1, 1);

    float2* cc_s = (float2*)(sm + SM_CC);
    float*  sx_s = (float*)(sm + SM_SX);
#pragma unroll
    for (int k = 0; k < 4; k++) cc_s[t + NTHR * k] = g_cc[t + NTHR * k];

    // ---- build X int8 tile in smem (swizzled 128B rows) + per-row scale ----
    {
        const float4* Xg = (const float4*)(X + (size_t)pbase * DIMS);
#pragma unroll
        for (int i = 0; i < 4; i++) {
            int idx = t + NTHR * i;          // 1024 chunks (16 dims each)
            int row = idx >> 3;
            int ch  = idx & 7;
            float f[16];
#pragma unroll
            for (int w = 0; w < 4; w++) {
                float4 v = Xg[row * 32 + ch * 4 + w];
                f[4*w] = v.x; f[4*w+1] = v.y; f[4*w+2] = v.z; f[4*w+3] = v.w;
            }
            float amax = 0.f;
#pragma unroll
            for (int e = 0; e < 16; e++) amax = fmaxf(amax, fabsf(f[e]));
#pragma unroll
            for (int off = 4; off; off >>= 1)
                amax = fmaxf(amax, __shfl_xor_sync(0xFFFFFFFFu, amax, off));
            float inv = amax > 0.f ? 127.f / amax : 0.f;
            uint4 u;
            u.x = pack4(__float2int_rn(f[ 0]*inv), __float2int_rn(f[ 1]*inv),
                        __float2int_rn(f[ 2]*inv), __float2int_rn(f[ 3]*inv));
            u.y = pack4(__float2int_rn(f[ 4]*inv), __float2int_rn(f[ 5]*inv),
                        __float2int_rn(f[ 6]*inv), __float2int_rn(f[ 7]*inv));
            u.z = pack4(__float2int_rn(f[ 8]*inv), __float2int_rn(f[ 9]*inv),
                        __float2int_rn(f[10]*inv), __float2int_rn(f[11]*inv));
            u.w = pack4(__float2int_rn(f[12]*inv), __float2int_rn(f[13]*inv),
                        __float2int_rn(f[14]*inv), __float2int_rn(f[15]*inv));
            uint32_t doff = (uint32_t)row * 128 + (uint32_t)((ch ^ (row & 7)) << 4);
            *(uint4*)(sm + SM_XI8 + doff) = u;
            if ((t & 7) == 0) sx_s[row] = amax * (1.f / 127.f);
        }
    }
    __syncthreads();

    const int arow0 = wm * 64 + (lane & 15);
    const uint32_t ak = (uint32_t)(lane >> 4);        // a k-half chunk
    const int brow0 = wn * 32 + (lane & 7) + ((lane >> 4) << 3);
    const uint32_t bk = (uint32_t)((lane >> 3) & 1);  // b k-half chunk
    const int r  = lane >> 2;

    float sxv[8];
#pragma unroll
    for (int mi = 0; mi < 4; mi++)
#pragma unroll
        for (int h = 0; h < 2; h++)
            sxv[mi * 2 + h] = sx_s[wm * 64 + mi * 16 + h * 8 + r];

    // per-slot top-2, u32 keys: (rankdis_bits & ~63) | local6  (64 clusters/slot)
    uint32_t k1[8], k2[8];
#pragma unroll
    for (int j = 0; j < 8; j++) { k1[j] = ~0u; k2[j] = ~0u; }

    for (int ct = 0; ct < NTILES; ct++) {
        if (ct < NTILES - 1) { CP_WAIT(1); } else { CP_WAIT(0); }
        __syncthreads();

        const uint32_t chb = base + SM_C + (ct & 1) * 16384;

        int acc[4][4][4];
#pragma unroll
        for (int mi = 0; mi < 4; mi++)
#pragma unroll
            for (int ni = 0; ni < 4; ni++)
#pragma unroll
                for (int q = 0; q < 4; q++) acc[mi][ni][q] = 0;

#pragma unroll
        for (int ks = 0; ks < 4; ks++) {     // k32 steps
            uint32_t ahi[4][4], bhi[4][2];
#pragma unroll
            for (int mi = 0; mi < 4; mi++) {
                int row = arow0 + mi * 16;
                uint32_t off = (uint32_t)row * 128 +
                               ((((uint32_t)ks * 2 + ak) ^ (uint32_t)(row & 7)) << 4);
                LDSM_X4(ahi[mi][0], ahi[mi][1], ahi[mi][2], ahi[mi][3], base + SM_XI8 + off);
            }
#pragma unroll
            for (int nh = 0; nh < 2; nh++) {
                int row = brow0 + nh * 16;
                uint32_t off = (uint32_t)row * 128 +
                               ((((uint32_t)ks * 2 + bk) ^ (uint32_t)(row & 7)) << 4);
                LDSM_X4(bhi[2 * nh][0], bhi[2 * nh][1], bhi[2 * nh + 1][0], bhi[2 * nh + 1][1],
                        chb + off);
            }
#pragma unroll
            for (int mi = 0; mi < 4; mi++)
#pragma unroll
                for (int ni = 0; ni < 4; ni++)
                    MMA_S8(acc[mi][ni], ahi[mi], bhi[ni]);
        }

        // ---- tile epilogue: rankdis = csqb - 2*sx*sc*acc, branchless top-2 ----
#pragma unroll
        for (int mi = 0; mi < 4; mi++)
#pragma unroll
            for (int ni = 0; ni < 4; ni++) {
                int cb = ct * TN + wn * 32 + ni * 8 + (lane & 3) * 2;
                float4 cc4 = *(const float4*)(cc_s + cb);  // {csqb0,scn0,csqb1,scn1}
#pragma unroll
                for (int q = 0; q < 4; q++) {
                    int j = mi * 2 + (q >> 1);
                    int q1 = q & 1;
                    float accf = (float)acc[mi][ni][q];
                    float prod = sxv[j] * (q1 ? cc4.w : cc4.y);
                    float dis  = fmaf(accf, prod, q1 ? cc4.z : cc4.x);
                    uint32_t local6 = (uint32_t)((ct << 3) | (ni << 1) | q1);
                    uint32_t key = (__float_as_uint(dis) & ~63u) | local6;
                    uint32_t m1 = min(k1[j], key), M1 = max(k1[j], key);
                    k1[j] = m1;
                    k2[j] = min(k2[j], M1);
                }
            }

        __syncthreads();
        if (ct + 2 < NTILES) cp_tile(ct + 2, ct & 1);
    }

    // ---- cross-thread candidate dump (reuse C buffer smem) ----
    uint32_t* rd = (uint32_t*)(sm + SM_C);             // [128 pts][32 keys] = 16KB
    int4*     cand_s = (int4*)(sm + SM_C + 16384);     // [128 pts] top-4 ids
    int slot = wn * 4 + (lane & 3);
#pragma unroll
    for (int mi = 0; mi < 4; mi++)
#pragma unroll
        for (int h = 0; h < 2; h++) {
            int j = mi * 2 + h;
            int row = wm * 64 + mi * 16 + h * 8 + r;
            rd[row * 32 + slot * 2 + 0] = k1[j];
            rd[row * 32 + slot * 2 + 1] = k2[j];
        }
    __syncthreads();

    // ---- phase A: per-point global top-4 id list (threads 0..127) ----
    if (t < TM) {
        uint32_t tk[4] = {~0u, ~0u, ~0u, ~0u};
        int      ti[4] = {0, 0, 0, 0};
#pragma unroll
        for (int s = 0; s < 16; s++) {
#pragma unroll
            for (int e = 0; e < 2; e++) {
                uint32_t key = rd[t * 32 + s * 2 + e];
                uint32_t local = key & 63u;
                int cid = (int)(((local >> 3) << 7) | ((uint32_t)(s >> 2) << 5) |
                                (((local >> 1) & 3u) << 3) | ((uint32_t)(s & 3) << 1) |
                                (local & 1u));
#pragma unroll
                for (int u = 0; u < 4; u++) {
                    bool p = key < tk[u];
                    uint32_t km = p ? key : tk[u];  uint32_t kM = p ? tk[u] : key;
                    int im = p ? cid : ti[u];       int iM = p ? ti[u] : cid;
                    tk[u] = km; ti[u] = im; key = kM; cid = iM;
                }
            }
        }
        cand_s[t] = make_int4(ti[0], ti[1], ti[2], ti[3]);
    }
    __syncthreads();

    // ---- phase B: warp-cooperative exact fp32 recheck (coalesced) ----
    {
        const int p0 = wid * 16;
        for (int pp = 0; pp < 16; pp++) {
            int p = p0 + pp;
            int4 cd = cand_s[p];
            float4 xv = ((const float4*)(X + (size_t)(pbase + p) * DIMS))[lane];
            int cids[4] = {cd.x, cd.y, cd.z, cd.w};
            float dot[4];
#pragma unroll
            for (int u = 0; u < 4; u++) {
                float4 cv = ((const float4*)(Cf + (size_t)cids[u] * DIMS))[lane];
                float s = xv.x * cv.x + xv.y * cv.y + xv.z * cv.z + xv.w * cv.w;
#pragma unroll
                for (int off = 16; off; off >>= 1)
                    s += __shfl_xor_sync(0xFFFFFFFFu, s, off);
                dot[u] = s;
            }
            if (lane == 0) {
                float bestd = 3.4e38f;
                int   bestc = KCL;
#pragma unroll
                for (int u = 0; u < 4; u++) {
                    float d = fmaf(dot[u], -2.f, cc_s[cids[u]].x);  // +64 bias const
                    if (d < bestd || (d == bestd && cids[u] < bestc)) {
                        bestd = d; bestc = cids[u];
                    }
                }
                out[pbase + p] = (float)bestc;   // __output__ is float32
            }
        }
    }
}

extern "C" void kernel_launch(void* const* d_in, const int* in_sizes, int n_in,
                              void* d_out, int out_size) {
    const float* X = (const float*)d_in[0];
    const float* C = (const float*)d_in[1];
    if (n_in >= 2 && in_sizes[0] < in_sizes[1]) {
        X = (const float*)d_in[1];
        C = (const float*)d_in[0];
    }
    float* out = (float*)d_out;

    cudaFuncSetAttribute(kmeans_mma_kernel,
                         cudaFuncAttributeMaxDynamicSharedMemorySize, SM_BYTES);

    prep_kernel<<<KCL / 256, 256>>>(C);
    kmeans_mma_kernel<<<NPTS / TM, NTHR, SM_BYTES>>>(X, C, out);
}

// round 15
// speedup vs baseline: 1.8132x; 1.8132x over previous
#include <cuda_runtime.h>
#include <cuda_bf16.h>
#include <cstdint>

#define NPTS 262144
#define DIMS 128
#define KCL  1024
#define TM   128
#define TN   128
#define NTILES (KCL / TN)   // 8
#define NTHR 256

// ---- smem map (dynamic, from 1KB-aligned base) ----
#define SM_XHI 0
#define SM_C   32768                 // 2 buffers x 32K (hi only)
#define SM_CSQ (32768 + 65536)       // 4KB (csq + 512 bias)
#define SM_BYTES (SM_CSQ + 4096 + 1024)

__device__ float g_csq[KCL];
__device__ __align__(16) unsigned char g_chi[KCL * DIMS * 2];  // bf16, row-major

// ---------------- PTX helpers (sm_80+ baseline ISA only) ----------------
__device__ __forceinline__ uint32_t smem_u32(const void* p) {
    uint32_t a;
    asm("{ .reg .u64 t; cvta.to.shared.u64 t, %1; cvt.u32.u64 %0, t; }" : "=r"(a) : "l"(p));
    return a;
}
#define LDSM_X4(r0, r1, r2, r3, addr) \
    asm volatile("ldmatrix.sync.aligned.m8n8.x4.shared.b16 {%0,%1,%2,%3}, [%4];" \
                 : "=r"(r0), "=r"(r1), "=r"(r2), "=r"(r3) : "r"(addr))
#define MMA_BF16(d, a, b) \
    asm volatile("mma.sync.aligned.m16n8k16.row.col.f32.bf16.bf16.f32 " \
                 "{%0,%1,%2,%3}, {%4,%5,%6,%7}, {%8,%9}, {%0,%1,%2,%3};" \
                 : "+f"((d)[0]), "+f"((d)[1]), "+f"((d)[2]), "+f"((d)[3]) \
                 : "r"((a)[0]), "r"((a)[1]), "r"((a)[2]), "r"((a)[3]), \
                   "r"((b)[0]), "r"((b)[1]))
#define CP_ASYNC16(dst, src) \
    asm volatile("cp.async.cg.shared.global [%0], [%1], 16;" :: "r"(dst), "l"(src))
#define CP_COMMIT() asm volatile("cp.async.commit_group;" ::: "memory")
#define CP_WAIT(n)  asm volatile("cp.async.wait_group %0;" :: "n"(n) : "memory")

// ---------------- prep kernel (biased csq + bf16 hi of C) ----------------
__global__ void prep_kernel(const float* __restrict__ C) {
    int idx = blockIdx.x * blockDim.x + threadIdx.x;   // over K*D
    if (idx < KCL * DIMS) {
        *(__nv_bfloat16*)(g_chi + (size_t)idx * 2) = __float2bfloat16(C[idx]);
    }
    if (idx < KCL) {
        const float4* row = (const float4*)(C + (size_t)idx * DIMS);
        float s = 0.f;
#pragma unroll
        for (int i = 0; i < DIMS / 4; i++) {
            float4 v = row[i];
            s += v.x * v.x + v.y * v.y + v.z * v.z + v.w * v.w;
        }
        g_csq[idx] = s + 512.f;   // bias keeps rank keys positive (dis' >= 512 - xsq > 0)
    }
}

// ---------------- main fused kernel ----------------
__global__ void __launch_bounds__(NTHR, 2)
kmeans_mma_kernel(const float* __restrict__ X, const float* __restrict__ Cf,
                  float* __restrict__ out)
{
    extern __shared__ unsigned char smraw[];
    uint32_t base = (smem_u32(smraw) + 1023u) & ~1023u;
    unsigned char* sm = smraw + (base - smem_u32(smraw));

    const int t    = threadIdx.x;
    const int lane = t & 31;
    const int wid  = t >> 5;
    const int wm   = wid & 1;    // warp row  (64 pts)
    const int wn   = wid >> 1;   // warp col  (32 clusters)
    const int pbase = blockIdx.x * TM;

    auto cp_tile = [&](int ct, int buf) {
        uint32_t dbase = base + SM_C + buf * 32768;
#pragma unroll
        for (int i = 0; i < 8; i++) {
            int idx = t + NTHR * i;          // 2048 uint4
            int row = idx >> 4;
            int c   = idx & 15;
            uint32_t doff = (uint32_t)row * 256 + (uint32_t)((c ^ (row & 7)) << 4);
            size_t   soff = (size_t)ct * 32768 + (size_t)row * 256 + (size_t)c * 16;
            CP_ASYNC16(dbase + doff, g_chi + soff);
        }
        CP_COMMIT();
    };
    cp_tile(0, 0);
    cp_tile(1, 1);

    float* csq_s = (float*)(sm + SM_CSQ);
#pragma unroll
    for (int k = 0; k < 4; k++) csq_s[t + NTHR * k] = g_csq[t + NTHR * k];

    // ---- build X hi tile in smem (swizzled 256B rows) ----
    {
        const float4* Xg = (const float4*)(X + (size_t)pbase * DIMS);
#pragma unroll
        for (int i = 0; i < 8; i++) {
            int idx = t + NTHR * i;          // 2048 chunks (8 dims each)
            int row = idx >> 4;
            int c   = idx & 15;
            float4 v0 = Xg[row * 32 + c * 2];
            float4 v1 = Xg[row * 32 + c * 2 + 1];
            float f[8] = {v0.x, v0.y, v0.z, v0.w, v1.x, v1.y, v1.z, v1.w};
            union { __nv_bfloat16 b[8]; uint4 u; } ph;
#pragma unroll
            for (int e = 0; e < 8; e++) ph.b[e] = __float2bfloat16(f[e]);
            uint32_t doff = (uint32_t)row * 256 + (uint32_t)((c ^ (row & 7)) << 4);
            *(uint4*)(sm + SM_XHI + doff) = ph.u;
        }
    }
    __syncthreads();

    const int arow0 = wm * 64 + (lane & 15);
    const uint32_t akb = (uint32_t)(lane >> 4) * 16;
    const int brow0 = wn * 32 + (lane & 7) + ((lane >> 4) << 3);
    const uint32_t bkb = (uint32_t)((lane >> 3) & 1) * 16;
    const int r  = lane >> 2;

    // per-slot top-2, u32 keys: (rank_bits & ~63) | local6  (xsq dropped: per-point const)
    uint32_t k1[8], k2[8];
#pragma unroll
    for (int j = 0; j < 8; j++) { k1[j] = ~0u; k2[j] = ~0u; }

    for (int ct = 0; ct < NTILES; ct++) {
        if (ct < NTILES - 1) { CP_WAIT(1); } else { CP_WAIT(0); }
        __syncthreads();

        const uint32_t chb = base + SM_C + (ct & 1) * 32768;

        float acc[4][4][4];
#pragma unroll
        for (int mi = 0; mi < 4; mi++)
#pragma unroll
            for (int ni = 0; ni < 4; ni++)
#pragma unroll
                for (int q = 0; q < 4; q++) acc[mi][ni][q] = 0.f;

#pragma unroll
        for (int ks = 0; ks < 8; ks++) {
            uint32_t ahi[4][4], bhi[4][2];
#pragma unroll
            for (int mi = 0; mi < 4; mi++) {
                int row = arow0 + mi * 16;
                uint32_t off = (uint32_t)row * 256 +
                               (((uint32_t)ks * 32 + akb) ^ (uint32_t)((row & 7) << 4));
                LDSM_X4(ahi[mi][0], ahi[mi][1], ahi[mi][2], ahi[mi][3], base + SM_XHI + off);
            }
#pragma unroll
            for (int nh = 0; nh < 2; nh++) {
                int row = brow0 + nh * 16;
                uint32_t off = (uint32_t)row * 256 +
                               (((uint32_t)ks * 32 + bkb) ^ (uint32_t)((row & 7) << 4));
                LDSM_X4(bhi[2 * nh][0], bhi[2 * nh][1], bhi[2 * nh + 1][0], bhi[2 * nh + 1][1],
                        chb + off);
            }
#pragma unroll
            for (int mi = 0; mi < 4; mi++)
#pragma unroll
                for (int ni = 0; ni < 4; ni++)
                    MMA_BF16(acc[mi][ni], ahi[mi], bhi[ni]);
        }

        // all warps done reading this C buffer -> start next tile's cp.async,
        // then do the register-only epilogue while it flies
        __syncthreads();
        if (ct + 2 < NTILES) cp_tile(ct + 2, ct & 1);

        // ---- tile epilogue: rank = csqb - 2*cross, branchless top-2 ----
#pragma unroll
        for (int mi = 0; mi < 4; mi++)
#pragma unroll
            for (int ni = 0; ni < 4; ni++) {
                int cb = ct * TN + wn * 32 + ni * 8 + (lane & 3) * 2;
                float2 cq = *(const float2*)(csq_s + cb);
#pragma unroll
                for (int q = 0; q < 4; q++) {
                    int j = mi * 2 + (q >> 1);
                    int q1 = q & 1;
                    float dis = fmaf(acc[mi][ni][q], -2.f, q1 ? cq.y : cq.x);
                    uint32_t local6 = (uint32_t)((ct << 3) | (ni << 1) | q1);
                    uint32_t key = (__float_as_uint(dis) & ~63u) | local6;
                    uint32_t m1 = min(k1[j], key), M1 = max(k1[j], key);
                    k1[j] = m1;
                    k2[j] = min(k2[j], M1);
                }
            }
    }

    __syncthreads();
    // ---- cross-thread candidate dump (reuse C buffer smem) ----
    uint32_t* rd = (uint32_t*)(sm + SM_C);             // [128 pts][32 keys] = 16KB
    int4*     cand_s = (int4*)(sm + SM_C + 16384);     // [128 pts] top-4 ids
    int slot = wn * 4 + (lane & 3);
#pragma unroll
    for (int mi = 0; mi < 4; mi++)
#pragma unroll
        for (int h = 0; h < 2; h++) {
            int j = mi * 2 + h;
            int row = wm * 64 + mi * 16 + h * 8 + r;
            rd[row * 32 + slot * 2 + 0] = k1[j];
            rd[row * 32 + slot * 2 + 1] = k2[j];
        }
    __syncthreads();

    // ---- phase A: per-point global top-4 id list (threads 0..127) ----
    if (t < TM) {
        uint32_t tk[4] = {~0u, ~0u, ~0u, ~0u};
        int      ti[4] = {0, 0, 0, 0};
#pragma unroll
        for (int s = 0; s < 16; s++) {
#pragma unroll
            for (int e = 0; e < 2; e++) {
                uint32_t key = rd[t * 32 + s * 2 + e];
                uint32_t local = key & 63u;
                int cid = (int)(((local >> 3) << 7) | ((uint32_t)(s >> 2) << 5) |
                                (((local >> 1) & 3u) << 3) | ((uint32_t)(s & 3) << 1) |
                                (local & 1u));
#pragma unroll
                for (int u = 0; u < 4; u++) {
                    bool p = key < tk[u];
                    uint32_t km = p ? key : tk[u];  uint32_t kM = p ? tk[u] : key;
                    int im = p ? cid : ti[u];       int iM = p ? ti[u] : cid;
                    tk[u] = km; ti[u] = im; key = kM; cid = iM;
                }
            }
        }
        cand_s[t] = make_int4(ti[0], ti[1], ti[2], ti[3]);
    }
    __syncthreads();

    // ---- phase B: warp-cooperative exact fp32 recheck (coalesced) ----
    // warp w handles points w*16 .. w*16+15; lanes cover one 128-float row
    {
        const int p0 = wid * 16;
#pragma unroll 2
        for (int pp = 0; pp < 16; pp++) {
            int p = p0 + pp;
            int4 cd = cand_s[p];
            float4 xv = ((const float4*)(X + (size_t)(pbase + p) * DIMS))[lane];
            int cids[4] = {cd.x, cd.y, cd.z, cd.w};
            float dot[4];
#pragma unroll
            for (int u = 0; u < 4; u++) {
                float4 cv = ((const float4*)(Cf + (size_t)cids[u] * DIMS))[lane];
                float s = xv.x * cv.x + xv.y * cv.y + xv.z * cv.z + xv.w * cv.w;
#pragma unroll
                for (int off = 16; off; off >>= 1)
                    s += __shfl_xor_sync(0xFFFFFFFFu, s, off);
                dot[u] = s;
            }
            if (lane == 0) {
                float bestd = 3.4e38f;
                int   bestc = KCL;
#pragma unroll
                for (int u = 0; u < 4; u++) {
                    float d = fmaf(dot[u], -2.f, csq_s[cids[u]]);  // shared +512 bias
                    if (d < bestd || (d == bestd && cids[u] < bestc)) {
                        bestd = d; bestc = cids[u];
                    }
                }
                out[pbase + p] = (float)bestc;   // __output__ is float32
            }
        }
    }
}

extern "C" void kernel_launch(void* const* d_in, const int* in_sizes, int n_in,
                              void* d_out, int out_size) {
    const float* X = (const float*)d_in[0];
    const float* C = (const float*)d_in[1];
    if (n_in >= 2 && in_sizes[0] < in_sizes[1]) {
        X = (const float*)d_in[1];
        C = (const float*)d_in[0];
    }
    float* out = (float*)d_out;

    cudaFuncSetAttribute(kmeans_mma_kernel,
                         cudaFuncAttributeMaxDynamicSharedMemorySize, SM_BYTES);

    prep_kernel<<<KCL * DIMS / 256, 256>>>(C);
    kmeans_mma_kernel<<<NPTS / TM, NTHR, SM_BYTES>>>(X, C, out);
}

// round 16
// speedup vs baseline: 1.8880x; 1.0413x over previous
#include <cuda_runtime.h>
#include <cuda_bf16.h>
#include <cstdint>

#define NPTS 262144
#define DIMS 128
#define KCL  1024
#define TM   128
#define TN   128
#define NTILES (KCL / TN)   // 8
#define NTHR 256

// ---- smem map (dynamic, from 1KB-aligned base) ----
#define SM_XHI 0
#define SM_C   32768                 // 2 buffers x 32K (hi only)
#define SM_CSQ (32768 + 65536)       // 4KB (csq + 512 bias)
#define SM_BYTES (SM_CSQ + 4096 + 1024)

__device__ float g_csq[KCL];
__device__ __align__(16) unsigned char g_chi[KCL * DIMS * 2];  // bf16, row-major

// ---------------- PTX helpers (sm_80+ baseline ISA only) ----------------
__device__ __forceinline__ uint32_t smem_u32(const void* p) {
    uint32_t a;
    asm("{ .reg .u64 t; cvta.to.shared.u64 t, %1; cvt.u32.u64 %0, t; }" : "=r"(a) : "l"(p));
    return a;
}
#define LDSM_X4(r0, r1, r2, r3, addr) \
    asm volatile("ldmatrix.sync.aligned.m8n8.x4.shared.b16 {%0,%1,%2,%3}, [%4];" \
                 : "=r"(r0), "=r"(r1), "=r"(r2), "=r"(r3) : "r"(addr))
#define MMA_BF16(d, a, b) \
    asm volatile("mma.sync.aligned.m16n8k16.row.col.f32.bf16.bf16.f32 " \
                 "{%0,%1,%2,%3}, {%4,%5,%6,%7}, {%8,%9}, {%0,%1,%2,%3};" \
                 : "+f"((d)[0]), "+f"((d)[1]), "+f"((d)[2]), "+f"((d)[3]) \
                 : "r"((a)[0]), "r"((a)[1]), "r"((a)[2]), "r"((a)[3]), \
                   "r"((b)[0]), "r"((b)[1]))
#define CP_ASYNC16(dst, src) \
    asm volatile("cp.async.cg.shared.global [%0], [%1], 16;" :: "r"(dst), "l"(src))
#define CP_COMMIT() asm volatile("cp.async.commit_group;" ::: "memory")
#define CP_WAIT(n)  asm volatile("cp.async.wait_group %0;" :: "n"(n) : "memory")

// ---------------- prep kernel (biased csq + bf16 hi of C) ----------------
__global__ void prep_kernel(const float* __restrict__ C) {
    int idx = blockIdx.x * blockDim.x + threadIdx.x;   // over K*D
    if (idx < KCL * DIMS) {
        *(__nv_bfloat16*)(g_chi + (size_t)idx * 2) = __float2bfloat16(C[idx]);
    }
    if (idx < KCL) {
        const float4* row = (const float4*)(C + (size_t)idx * DIMS);
        float s = 0.f;
#pragma unroll
        for (int i = 0; i < DIMS / 4; i++) {
            float4 v = row[i];
            s += v.x * v.x + v.y * v.y + v.z * v.z + v.w * v.w;
        }
        g_csq[idx] = s + 512.f;   // bias keeps rank keys positive (dis' >= 512 - xsq > 0)
    }
}

// ---------------- main fused kernel ----------------
__global__ void __launch_bounds__(NTHR, 2)
kmeans_mma_kernel(const float* __restrict__ X, const float* __restrict__ Cf,
                  float* __restrict__ out)
{
    extern __shared__ unsigned char smraw[];
    uint32_t base = (smem_u32(smraw) + 1023u) & ~1023u;
    unsigned char* sm = smraw + (base - smem_u32(smraw));

    const int t    = threadIdx.x;
    const int lane = t & 31;
    const int wid  = t >> 5;
    const int wm   = wid & 1;    // warp row  (64 pts)
    const int wn   = wid >> 1;   // warp col  (32 clusters)
    const int pbase = blockIdx.x * TM;

    auto cp_tile = [&](int ct, int buf) {
        uint32_t dbase = base + SM_C + buf * 32768;
#pragma unroll
        for (int i = 0; i < 8; i++) {
            int idx = t + NTHR * i;          // 2048 uint4
            int row = idx >> 4;
            int c   = idx & 15;
            uint32_t doff = (uint32_t)row * 256 + (uint32_t)((c ^ (row & 7)) << 4);
            size_t   soff = (size_t)ct * 32768 + (size_t)row * 256 + (size_t)c * 16;
            CP_ASYNC16(dbase + doff, g_chi + soff);
        }
        CP_COMMIT();
    };
    cp_tile(0, 0);
    cp_tile(1, 1);

    float* csq_s = (float*)(sm + SM_CSQ);
#pragma unroll
    for (int k = 0; k < 4; k++) csq_s[t + NTHR * k] = g_csq[t + NTHR * k];

    // ---- build X hi tile in smem (swizzled 256B rows), packed bf16x2 converts ----
    {
        const float4* Xg = (const float4*)(X + (size_t)pbase * DIMS);
#pragma unroll
        for (int i = 0; i < 8; i++) {
            int idx = t + NTHR * i;          // 2048 chunks (8 dims each)
            int row = idx >> 4;
            int c   = idx & 15;
            float4 v0 = Xg[row * 32 + c * 2];
            float4 v1 = Xg[row * 32 + c * 2 + 1];
            union { __nv_bfloat162 b2[4]; uint4 u; } ph;
            ph.b2[0] = __floats2bfloat162_rn(v0.x, v0.y);
            ph.b2[1] = __floats2bfloat162_rn(v0.z, v0.w);
            ph.b2[2] = __floats2bfloat162_rn(v1.x, v1.y);
            ph.b2[3] = __floats2bfloat162_rn(v1.z, v1.w);
            uint32_t doff = (uint32_t)row * 256 + (uint32_t)((c ^ (row & 7)) << 4);
            *(uint4*)(sm + SM_XHI + doff) = ph.u;
        }
    }
    __syncthreads();

    const int arow0 = wm * 64 + (lane & 15);
    const uint32_t akb = (uint32_t)(lane >> 4) * 16;
    const int brow0 = wn * 32 + (lane & 7) + ((lane >> 4) << 3);
    const uint32_t bkb = (uint32_t)((lane >> 3) & 1) * 16;
    const int r  = lane >> 2;

    // per-slot top-2, u32 keys: (rank_bits & ~63) | local6
    uint32_t k1[8], k2[8];
#pragma unroll
    for (int j = 0; j < 8; j++) { k1[j] = ~0u; k2[j] = ~0u; }

    for (int ct = 0; ct < NTILES; ct++) {
        if (ct < NTILES - 1) { CP_WAIT(1); } else { CP_WAIT(0); }
        __syncthreads();

        const uint32_t chb = base + SM_C + (ct & 1) * 32768;

        float acc[4][4][4];
#pragma unroll
        for (int mi = 0; mi < 4; mi++)
#pragma unroll
            for (int ni = 0; ni < 4; ni++)
#pragma unroll
                for (int q = 0; q < 4; q++) acc[mi][ni][q] = 0.f;

#pragma unroll
        for (int ks = 0; ks < 8; ks++) {
            uint32_t ahi[4][4], bhi[4][2];
#pragma unroll
            for (int mi = 0; mi < 4; mi++) {
                int row = arow0 + mi * 16;
                uint32_t off = (uint32_t)row * 256 +
                               (((uint32_t)ks * 32 + akb) ^ (uint32_t)((row & 7) << 4));
                LDSM_X4(ahi[mi][0], ahi[mi][1], ahi[mi][2], ahi[mi][3], base + SM_XHI + off);
            }
#pragma unroll
            for (int nh = 0; nh < 2; nh++) {
                int row = brow0 + nh * 16;
                uint32_t off = (uint32_t)row * 256 +
                               (((uint32_t)ks * 32 + bkb) ^ (uint32_t)((row & 7) << 4));
                LDSM_X4(bhi[2 * nh][0], bhi[2 * nh][1], bhi[2 * nh + 1][0], bhi[2 * nh + 1][1],
                        chb + off);
            }
#pragma unroll
            for (int mi = 0; mi < 4; mi++)
#pragma unroll
                for (int ni = 0; ni < 4; ni++)
                    MMA_BF16(acc[mi][ni], ahi[mi], bhi[ni]);
        }

        // all warps done reading this C buffer -> start next tile's cp.async,
        // then do the register-only epilogue while it flies
        __syncthreads();
        if (ct + 2 < NTILES) cp_tile(ct + 2, ct & 1);

        // ---- tile epilogue: rank = csqb - 2*cross, PAIR-MIN branchless top-2 ----
#pragma unroll
        for (int mi = 0; mi < 4; mi++)
#pragma unroll
            for (int ni = 0; ni < 4; ni++) {
                int cb = ct * TN + wn * 32 + ni * 8 + (lane & 3) * 2;
                float2 cq = *(const float2*)(csq_s + cb);
                uint32_t l6a = (uint32_t)((ct << 3) | (ni << 1));
#pragma unroll
                for (int h = 0; h < 2; h++) {
                    int j = mi * 2 + h;
                    float dA = fmaf(acc[mi][ni][2 * h],     -2.f, cq.x);
                    float dB = fmaf(acc[mi][ni][2 * h + 1], -2.f, cq.y);
                    uint32_t kA = (__float_as_uint(dA) & ~63u) | l6a;
                    uint32_t kB = (__float_as_uint(dB) & ~63u) | (l6a | 1u);
                    uint32_t k  = min(kA, kB);   // in-pair winner (id in low bits)
                    uint32_t m1 = min(k1[j], k), M1 = max(k1[j], k);
                    k1[j] = m1;
                    k2[j] = min(k2[j], M1);
                }
            }
    }

    __syncthreads();
    // ---- cross-thread candidate dump (reuse C buffer smem) ----
    uint32_t* rd = (uint32_t*)(sm + SM_C);             // [128 pts][32 keys] = 16KB
    int4*     cand_s = (int4*)(sm + SM_C + 16384);     // [128 pts] top-4 ids
    int slot = wn * 4 + (lane & 3);
#pragma unroll
    for (int mi = 0; mi < 4; mi++)
#pragma unroll
        for (int h = 0; h < 2; h++) {
            int j = mi * 2 + h;
            int row = wm * 64 + mi * 16 + h * 8 + r;
            rd[row * 32 + slot * 2 + 0] = k1[j];
            rd[row * 32 + slot * 2 + 1] = k2[j];
        }
    __syncthreads();

    // ---- phase A: per-point global top-4 id list (threads 0..127) ----
    if (t < TM) {
        uint32_t tk[4] = {~0u, ~0u, ~0u, ~0u};
        int      ti[4] = {0, 0, 0, 0};
#pragma unroll
        for (int s = 0; s < 16; s++) {
#pragma unroll
            for (int e = 0; e < 2; e++) {
                uint32_t key = rd[t * 32 + s * 2 + e];
                uint32_t local = key & 63u;
                int cid = (int)(((local >> 3) << 7) | ((uint32_t)(s >> 2) << 5) |
                                (((local >> 1) & 3u) << 3) | ((uint32_t)(s & 3) << 1) |
                                (local & 1u));
#pragma unroll
                for (int u = 0; u < 4; u++) {
                    bool p = key < tk[u];
                    uint32_t km = p ? key : tk[u];  uint32_t kM = p ? tk[u] : key;
                    int im = p ? cid : ti[u];       int iM = p ? ti[u] : cid;
                    tk[u] = km; ti[u] = im; key = kM; cid = iM;
                }
            }
        }
        cand_s[t] = make_int4(ti[0], ti[1], ti[2], ti[3]);
    }
    __syncthreads();

    // ---- phase B: warp-cooperative exact fp32 recheck (coalesced) ----
    {
        const int p0 = wid * 16;
#pragma unroll 2
        for (int pp = 0; pp < 16; pp++) {
            int p = p0 + pp;
            int4 cd = cand_s[p];
            float4 xv = ((const float4*)(X + (size_t)(pbase + p) * DIMS))[lane];
            int cids[4] = {cd.x, cd.y, cd.z, cd.w};
            float dot[4];
#pragma unroll
            for (int u = 0; u < 4; u++) {
                float4 cv = ((const float4*)(Cf + (size_t)cids[u] * DIMS))[lane];
                float s = xv.x * cv.x + xv.y * cv.y + xv.z * cv.z + xv.w * cv.w;
#pragma unroll
                for (int off = 16; off; off >>= 1)
                    s += __shfl_xor_sync(0xFFFFFFFFu, s, off);
                dot[u] = s;
            }
            if (lane == 0) {
                float bestd = 3.4e38f;
                int   bestc = KCL;
#pragma unroll
                for (int u = 0; u < 4; u++) {
                    float d = fmaf(dot[u], -2.f, csq_s[cids[u]]);  // shared +512 bias
                    if (d < bestd || (d == bestd && cids[u] < bestc)) {
                        bestd = d; bestc = cids[u];
                    }
                }
                out[pbase + p] = (float)bestc;   // __output__ is float32
            }
        }
    }
}

extern "C" void kernel_launch(void* const* d_in, const int* in_sizes, int n_in,
                              void* d_out, int out_size) {
    const float* X = (const float*)d_in[0];
    const float* C = (const float*)d_in[1];
    if (n_in >= 2 && in_sizes[0] < in_sizes[1]) {
        X = (const float*)d_in[1];
        C = (const float*)d_in[0];
    }
    float* out = (float*)d_out;

    cudaFuncSetAttribute(kmeans_mma_kernel,
                         cudaFuncAttributeMaxDynamicSharedMemorySize, SM_BYTES);

    prep_kernel<<<KCL * DIMS / 256, 256>>>(C);
    kmeans_mma_kernel<<<NPTS / TM, NTHR, SM_BYTES>>>(X, C, out);
}

// round 17
// speedup vs baseline: 1.9127x; 1.0131x over previous
#include <cuda_runtime.h>
#include <cuda_bf16.h>
#include <cstdint>

#define NPTS 262144
#define DIMS 128
#define KCL  1024
#define TM   128
#define TN   128
#define NTILES (KCL / TN)   // 8
#define NTHR 256

// ---- smem map (dynamic, from 1KB-aligned base) ----
#define SM_XHI 0
#define SM_C   32768                 // 2 buffers x 32K (hi only)
#define SM_CSQ (32768 + 65536)       // 4KB (csq + 512 bias)
#define SM_BYTES (SM_CSQ + 4096 + 1024)

__device__ float g_csq[KCL];
__device__ __align__(16) unsigned char g_chi[KCL * DIMS * 2];  // bf16, row-major

// ---------------- PTX helpers (sm_80+ baseline ISA only) ----------------
__device__ __forceinline__ uint32_t smem_u32(const void* p) {
    uint32_t a;
    asm("{ .reg .u64 t; cvta.to.shared.u64 t, %1; cvt.u32.u64 %0, t; }" : "=r"(a) : "l"(p));
    return a;
}
#define LDSM_X4(r0, r1, r2, r3, addr) \
    asm volatile("ldmatrix.sync.aligned.m8n8.x4.shared.b16 {%0,%1,%2,%3}, [%4];" \
                 : "=r"(r0), "=r"(r1), "=r"(r2), "=r"(r3) : "r"(addr))
#define MMA_BF16(d, a, b) \
    asm volatile("mma.sync.aligned.m16n8k16.row.col.f32.bf16.bf16.f32 " \
                 "{%0,%1,%2,%3}, {%4,%5,%6,%7}, {%8,%9}, {%0,%1,%2,%3};" \
                 : "+f"((d)[0]), "+f"((d)[1]), "+f"((d)[2]), "+f"((d)[3]) \
                 : "r"((a)[0]), "r"((a)[1]), "r"((a)[2]), "r"((a)[3]), \
                   "r"((b)[0]), "r"((b)[1]))
#define CP_ASYNC16(dst, src) \
    asm volatile("cp.async.cg.shared.global [%0], [%1], 16;" :: "r"(dst), "l"(src))
#define CP_COMMIT() asm volatile("cp.async.commit_group;" ::: "memory")
#define CP_WAIT(n)  asm volatile("cp.async.wait_group %0;" :: "n"(n) : "memory")

// ---------------- prep kernel (biased csq + bf16 hi of C) ----------------
__global__ void prep_kernel(const float* __restrict__ C) {
    int idx = blockIdx.x * blockDim.x + threadIdx.x;   // over K*D
    if (idx < KCL * DIMS) {
        *(__nv_bfloat16*)(g_chi + (size_t)idx * 2) = __float2bfloat16(C[idx]);
    }
    if (idx < KCL) {
        const float4* row = (const float4*)(C + (size_t)idx * DIMS);
        float s = 0.f;
#pragma unroll
        for (int i = 0; i < DIMS / 4; i++) {
            float4 v = row[i];
            s += v.x * v.x + v.y * v.y + v.z * v.z + v.w * v.w;
        }
        g_csq[idx] = s + 512.f;   // bias keeps rank keys positive
    }
}

// ---------------- main fused kernel ----------------
__global__ void __launch_bounds__(NTHR, 2)
kmeans_mma_kernel(const float* __restrict__ X, const float* __restrict__ Cf,
                  float* __restrict__ out)
{
    extern __shared__ unsigned char smraw[];
    uint32_t base = (smem_u32(smraw) + 1023u) & ~1023u;
    unsigned char* sm = smraw + (base - smem_u32(smraw));

    const int t    = threadIdx.x;
    const int lane = t & 31;
    const int wid  = t >> 5;
    const int wm   = wid & 1;    // warp row  (64 pts)
    const int wn   = wid >> 1;   // warp col  (32 clusters)
    const int pbase = blockIdx.x * TM;

    auto cp_tile = [&](int ct, int buf) {
        uint32_t dbase = base + SM_C + buf * 32768;
#pragma unroll
        for (int i = 0; i < 8; i++) {
            int idx = t + NTHR * i;          // 2048 uint4
            int row = idx >> 4;
            int c   = idx & 15;
            uint32_t doff = (uint32_t)row * 256 + (uint32_t)((c ^ (row & 7)) << 4);
            size_t   soff = (size_t)ct * 32768 + (size_t)row * 256 + (size_t)c * 16;
            CP_ASYNC16(dbase + doff, g_chi + soff);
        }
        CP_COMMIT();
    };
    cp_tile(0, 0);
    cp_tile(1, 1);

    float* csq_s = (float*)(sm + SM_CSQ);
#pragma unroll
    for (int k = 0; k < 4; k++) csq_s[t + NTHR * k] = g_csq[t + NTHR * k];

    // ---- build X hi tile in smem (swizzled 256B rows), packed bf16x2 converts ----
    {
        const float4* Xg = (const float4*)(X + (size_t)pbase * DIMS);
#pragma unroll
        for (int i = 0; i < 8; i++) {
            int idx = t + NTHR * i;          // 2048 chunks (8 dims each)
            int row = idx >> 4;
            int c   = idx & 15;
            float4 v0 = Xg[row * 32 + c * 2];
            float4 v1 = Xg[row * 32 + c * 2 + 1];
            union { __nv_bfloat162 b2[4]; uint4 u; } ph;
            ph.b2[0] = __floats2bfloat162_rn(v0.x, v0.y);
            ph.b2[1] = __floats2bfloat162_rn(v0.z, v0.w);
            ph.b2[2] = __floats2bfloat162_rn(v1.x, v1.y);
            ph.b2[3] = __floats2bfloat162_rn(v1.z, v1.w);
            uint32_t doff = (uint32_t)row * 256 + (uint32_t)((c ^ (row & 7)) << 4);
            *(uint4*)(sm + SM_XHI + doff) = ph.u;
        }
    }
    __syncthreads();

    const int arow0 = wm * 64 + (lane & 15);
    const uint32_t akb = (uint32_t)(lane >> 4) * 16;
    const int brow0 = wn * 32 + (lane & 7) + ((lane >> 4) << 3);
    const uint32_t bkb = (uint32_t)((lane >> 3) & 1) * 16;
    const int r  = lane >> 2;

    // ---- partial A-hoist: fragments for ks=0,1 live for the whole kernel ----
    uint32_t ah0[4][4], ah1[4][4];
#pragma unroll
    for (int mi = 0; mi < 4; mi++) {
        int row = arow0 + mi * 16;
        uint32_t sw = (uint32_t)((row & 7) << 4);
        uint32_t off0 = (uint32_t)row * 256 + ((0u * 32 + akb) ^ sw);
        uint32_t off1 = (uint32_t)row * 256 + ((1u * 32 + akb) ^ sw);
        LDSM_X4(ah0[mi][0], ah0[mi][1], ah0[mi][2], ah0[mi][3], base + SM_XHI + off0);
        LDSM_X4(ah1[mi][0], ah1[mi][1], ah1[mi][2], ah1[mi][3], base + SM_XHI + off1);
    }

    // per-slot top-2, u32 keys: (rank_bits & ~63) | local6
    uint32_t k1[8], k2[8];
#pragma unroll
    for (int j = 0; j < 8; j++) { k1[j] = ~0u; k2[j] = ~0u; }

    for (int ct = 0; ct < NTILES; ct++) {
        if (ct < NTILES - 1) { CP_WAIT(1); } else { CP_WAIT(0); }
        __syncthreads();

        const uint32_t chb = base + SM_C + (ct & 1) * 32768;

        float acc[4][4][4];
#pragma unroll
        for (int mi = 0; mi < 4; mi++)
#pragma unroll
            for (int ni = 0; ni < 4; ni++)
#pragma unroll
                for (int q = 0; q < 4; q++) acc[mi][ni][q] = 0.f;

#pragma unroll
        for (int ks = 0; ks < 8; ks++) {
            uint32_t atmp[4][4], bhi[4][2];
            if (ks >= 2) {
#pragma unroll
                for (int mi = 0; mi < 4; mi++) {
                    int row = arow0 + mi * 16;
                    uint32_t off = (uint32_t)row * 256 +
                                   (((uint32_t)ks * 32 + akb) ^ (uint32_t)((row & 7) << 4));
                    LDSM_X4(atmp[mi][0], atmp[mi][1], atmp[mi][2], atmp[mi][3],
                            base + SM_XHI + off);
                }
            }
#pragma unroll
            for (int nh = 0; nh < 2; nh++) {
                int row = brow0 + nh * 16;
                uint32_t off = (uint32_t)row * 256 +
                               (((uint32_t)ks * 32 + bkb) ^ (uint32_t)((row & 7) << 4));
                LDSM_X4(bhi[2 * nh][0], bhi[2 * nh][1], bhi[2 * nh + 1][0], bhi[2 * nh + 1][1],
                        chb + off);
            }
#pragma unroll
            for (int mi = 0; mi < 4; mi++)
#pragma unroll
                for (int ni = 0; ni < 4; ni++) {
                    if (ks == 0)      MMA_BF16(acc[mi][ni], ah0[mi],  bhi[ni]);
                    else if (ks == 1) MMA_BF16(acc[mi][ni], ah1[mi],  bhi[ni]);
                    else              MMA_BF16(acc[mi][ni], atmp[mi], bhi[ni]);
                }
        }

        // all warps done reading this C buffer -> start next tile's cp.async,
        // then do the register-only epilogue while it flies
        __syncthreads();
        if (ct + 2 < NTILES) cp_tile(ct + 2, ct & 1);

        // ---- tile epilogue: rank = csqb - 2*cross, PAIR-MIN branchless top-2 ----
#pragma unroll
        for (int mi = 0; mi < 4; mi++)
#pragma unroll
            for (int ni = 0; ni < 4; ni++) {
                int cb = ct * TN + wn * 32 + ni * 8 + (lane & 3) * 2;
                float2 cq = *(const float2*)(csq_s + cb);
                uint32_t l6a = (uint32_t)((ct << 3) | (ni << 1));
#pragma unroll
                for (int h = 0; h < 2; h++) {
                    int j = mi * 2 + h;
                    float dA = fmaf(acc[mi][ni][2 * h],     -2.f, cq.x);
                    float dB = fmaf(acc[mi][ni][2 * h + 1], -2.f, cq.y);
                    uint32_t kA = (__float_as_uint(dA) & ~63u) | l6a;
                    uint32_t kB = (__float_as_uint(dB) & ~63u) | (l6a | 1u);
                    uint32_t k  = min(kA, kB);   // in-pair winner (id in low bits)
                    uint32_t m1 = min(k1[j], k), M1 = max(k1[j], k);
                    k1[j] = m1;
                    k2[j] = min(k2[j], M1);
                }
            }
    }

    __syncthreads();
    // ---- cross-thread candidate dump (packed uint2, reuse C buffer smem) ----
    uint2* rd2 = (uint2*)(sm + SM_C);                  // [128 pts][16 slots] = 16KB
    int4*  cand_s = (int4*)(sm + SM_C + 16384);        // [128 pts] top-4 ids
    int slot = wn * 4 + (lane & 3);
#pragma unroll
    for (int mi = 0; mi < 4; mi++)
#pragma unroll
        for (int h = 0; h < 2; h++) {
            int j = mi * 2 + h;
            int row = wm * 64 + mi * 16 + h * 8 + r;
            rd2[row * 16 + slot] = make_uint2(k1[j], k2[j]);
        }
    __syncthreads();

    // ---- phase A: per-point global top-4 id list (threads 0..127) ----
    if (t < TM) {
        uint32_t tk[4] = {~0u, ~0u, ~0u, ~0u};
        int      ti[4] = {0, 0, 0, 0};
#pragma unroll
        for (int s = 0; s < 16; s++) {
            uint2 kk = rd2[t * 16 + s];
            uint32_t keys[2] = {kk.x, kk.y};
#pragma unroll
            for (int e = 0; e < 2; e++) {
                uint32_t key = keys[e];
                uint32_t local = key & 63u;
                int cid = (int)(((local >> 3) << 7) | ((uint32_t)(s >> 2) << 5) |
                                (((local >> 1) & 3u) << 3) | ((uint32_t)(s & 3) << 1) |
                                (local & 1u));
#pragma unroll
                for (int u = 0; u < 4; u++) {
                    bool p = key < tk[u];
                    uint32_t km = p ? key : tk[u];  uint32_t kM = p ? tk[u] : key;
                    int im = p ? cid : ti[u];       int iM = p ? ti[u] : cid;
                    tk[u] = km; ti[u] = im; key = kM; cid = iM;
                }
            }
        }
        cand_s[t] = make_int4(ti[0], ti[1], ti[2], ti[3]);
    }
    __syncthreads();

    // ---- phase B: warp-cooperative exact fp32 recheck (coalesced) ----
    {
        const int p0 = wid * 16;
#pragma unroll 2
        for (int pp = 0; pp < 16; pp++) {
            int p = p0 + pp;
            int4 cd = cand_s[p];
            float4 xv = ((const float4*)(X + (size_t)(pbase + p) * DIMS))[lane];
            int cids[4] = {cd.x, cd.y, cd.z, cd.w};
            float dot[4];
#pragma unroll
            for (int u = 0; u < 4; u++) {
                float4 cv = ((const float4*)(Cf + (size_t)cids[u] * DIMS))[lane];
                float s = xv.x * cv.x + xv.y * cv.y + xv.z * cv.z + xv.w * cv.w;
#pragma unroll
                for (int off = 16; off; off >>= 1)
                    s += __shfl_xor_sync(0xFFFFFFFFu, s, off);
                dot[u] = s;
            }
            if (lane == 0) {
                float bestd = 3.4e38f;
                int   bestc = KCL;
#pragma unroll
                for (int u = 0; u < 4; u++) {
                    float d = fmaf(dot[u], -2.f, csq_s[cids[u]]);  // shared +512 bias
                    if (d < bestd || (d == bestd && cids[u] < bestc)) {
                        bestd = d; bestc = cids[u];
                    }
                }
                out[pbase + p] = (float)bestc;   // __output__ is float32
            }
        }
    }
}

extern "C" void kernel_launch(void* const* d_in, const int* in_sizes, int n_in,
                              void* d_out, int out_size) {
    const float* X = (const float*)d_in[0];
    const float* C = (const float*)d_in[1];
    if (n_in >= 2 && in_sizes[0] < in_sizes[1]) {
        X = (const float*)d_in[1];
        C = (const float*)d_in[0];
    }
    float* out = (float*)d_out;

    cudaFuncSetAttribute(kmeans_mma_kernel,
                         cudaFuncAttributeMaxDynamicSharedMemorySize, SM_BYTES);

    prep_kernel<<<KCL * DIMS / 256, 256>>>(C);
    kmeans_mma_kernel<<<NPTS / TM, NTHR, SM_BYTES>>>(X, C, out);
}